// round 17
// baseline (speedup 1.0000x reference)
#include <cuda_runtime.h>
#include <cuda_fp16.h>
#include <math.h>
#include <stdint.h>

#define NUM_EMBED 8192
#define EMBED_DIM 64
#define BB 8
#define HH 64
#define WW 64
#define N_TOK   (BB*HH*WW)            /* 32768 */
#define N_ELEM  (BB*EMBED_DIM*HH*WW)  /* 2097152 */
#define HW      (HH*WW)               /* 4096 */
#define N_PART  2048

#define M_CTA   128                   /* tokens per CTA (stage 1) */
#define TN      128                   /* codes per tile */
#define N_TILES (NUM_EMBED / TN)      /* 64 */
#define NT1     256                   /* stage-1 threads (8 warps) */

// stage-1 SMEM (from 1024-aligned base):
//   A0  @ 0     : 128 rows x 128B (fp16 z, swizzled)   16384
//   B   @ 16384 : 2 bufs x [128 x 128B]                32768
//   TAB @ 49152 : 128 rows x 2 groups x float4         4096
#define OFF_B    16384
#define OFF_TAB  49152
#define SMEM1_BYTES (OFF_TAB + 4096 + 1024)

#define SWZ(o) ((o) ^ (((o) >> 3) & 0x70))

// ---------------------------------------------------------------------------
// device scratch
// ---------------------------------------------------------------------------
__device__ __align__(16) __half g_e0[NUM_EMBED * EMBED_DIM];   // fp16 normalized codebook
__device__ __align__(16) float  g_enf[NUM_EMBED * EMBED_DIM];  // fp32 normalized codebook
__device__ int   g_idx[N_TOK];
__device__ int   g_flist[N_TOK];
__device__ int   g_nflag;
__device__ int   g_hist[NUM_EMBED];
__device__ float g_partial[N_PART];

// ---------------------------------------------------------------------------
// asm helpers (plain sm_80+ only)
// ---------------------------------------------------------------------------
__device__ __forceinline__ uint32_t smem_u32(const void* p) {
    uint32_t a;
    asm("{ .reg .u64 t; cvta.to.shared.u64 t, %1; cvt.u32.u64 %0, t; }" : "=r"(a) : "l"(p));
    return a;
}
#define LDSM_X4(r, addr)                                                         \
    asm volatile("ldmatrix.sync.aligned.m8n8.x4.shared.b16 {%0,%1,%2,%3}, [%4];" \
        : "=r"((r)[0]), "=r"((r)[1]), "=r"((r)[2]), "=r"((r)[3]) : "r"(addr))

#define MMA_16816(c, a, b0, b1)                                                  \
    asm volatile("mma.sync.aligned.m16n8k16.row.col.f32.f16.f16.f32 "            \
        "{%0,%1,%2,%3}, {%4,%5,%6,%7}, {%8,%9}, {%0,%1,%2,%3};"                  \
        : "+f"((c)[0]), "+f"((c)[1]), "+f"((c)[2]), "+f"((c)[3])                 \
        : "r"((a)[0]), "r"((a)[1]), "r"((a)[2]), "r"((a)[3]), "r"(b0), "r"(b1))

#define CP_ASYNC16(saddr, gptr)                                                  \
    asm volatile("cp.async.cg.shared.global [%0], [%1], 16;" :: "r"(saddr), "l"(gptr))
#define CP_COMMIT()  asm volatile("cp.async.commit_group;")
#define CP_WAIT1()   asm volatile("cp.async.wait_group 1;")
#define CP_WAIT0()   asm volatile("cp.async.wait_group 0;")

// strict (value desc, index asc) ordering
__device__ __forceinline__ bool vgt(float u, int ui, float v, int vi) {
    return (u > v) || (u == v && ui < vi);
}

// merge two (v1,i1,v2,i2,v3) tuples; each sorted desc. Result in a-side.
// Indices packed: low16 = i1, high16 = i2.
__device__ __forceinline__ void merge5(
    float& a1, float& a2, float& a3, uint32_t& ap,
    float  b1, float  b2, float  b3, uint32_t bp)
{
    int ai1 = (int)(ap & 0xFFFFu), ai2 = (int)(ap >> 16);
    int bi1 = (int)(bp & 0xFFFFu), bi2 = (int)(bp >> 16);
    float r1, r2, r3; int ri1, ri2;
    if (vgt(a1, ai1, b1, bi1)) {
        r1 = a1; ri1 = ai1;
        if (vgt(a2, ai2, b1, bi1)) { r2 = a2; ri2 = ai2; r3 = fmaxf(a3, b1); }
        else                       { r2 = b1; ri2 = bi1; r3 = fmaxf(a2, b2); }
    } else {
        r1 = b1; ri1 = bi1;
        if (vgt(b2, bi2, a1, ai1)) { r2 = b2; ri2 = bi2; r3 = fmaxf(b3, a1); }
        else                       { r2 = a1; ri2 = ai1; r3 = fmaxf(b2, a2); }
    }
    a1 = r1; a2 = r2; a3 = r3;
    ap = (uint32_t)ri1 | ((uint32_t)ri2 << 16);
}

// ---------------------------------------------------------------------------
// Kernel 1: zero scratch + normalize codebook -> fp16 + fp32
// ---------------------------------------------------------------------------
__global__ void vq_prep_embed(const float* __restrict__ emb) {
    int gid = blockIdx.x * 256 + threadIdx.x;
    if (threadIdx.x < 8) g_hist[blockIdx.x * 8 + threadIdx.x] = 0;
    if (gid == 0) g_nflag = 0;

    int wid  = gid >> 5;
    int lane = threadIdx.x & 31;
    if (wid >= NUM_EMBED) return;
    const float* row = emb + wid * EMBED_DIM;
    float x0 = row[lane];
    float x1 = row[lane + 32];
    float s = x0 * x0 + x1 * x1;
    #pragma unroll
    for (int o = 16; o > 0; o >>= 1) s += __shfl_xor_sync(0xFFFFFFFFu, s, o);
    float inv = 1.0f / sqrtf(s);
    #pragma unroll
    for (int h = 0; h < 2; h++) {
        int c = lane + h * 32;
        float xn = (h ? x1 : x0) * inv;
        g_e0[wid * EMBED_DIM + c]  = __float2half(xn);
        g_enf[wid * EMBED_DIM + c] = xn;
    }
}

// ---------------------------------------------------------------------------
// Kernel 2 (stage 1): 1-term fp16 GEMM + screened top-2-idx/top-3-val
// tracking + exact 2-candidate rescore certificate.
// 256 threads = 8 warps, 4(M) x 2(N). Warp tile 32 x 64. 2 CTAs/SM.
// ---------------------------------------------------------------------------
__global__ __launch_bounds__(NT1, 2)
void vq_argmax_mma(const float* __restrict__ z, float* __restrict__ idx_out_f) {
    extern __shared__ char dsm_raw[];
    const uint32_t raw   = smem_u32(dsm_raw);
    const uint32_t abase = (raw + 1023u) & ~1023u;
    char* sm = dsm_raw + (abase - raw);

    const int tid    = threadIdx.x;
    const int lane   = tid & 31;
    const int warp_m = (tid >> 5) & 3;
    const int warp_n = tid >> 7;
    const int wm0    = warp_m * 32;
    const int cn0    = warp_n * 64;
    const int grp    = lane >> 3;

    const int m0  = blockIdx.x * M_CTA;
    const int b   = m0 >> 12;
    const int hw0 = m0 & 4095;

    auto load_b = [&](int t, int p) {
        const int n0 = t * TN;
        const uint32_t sb = abase + OFF_B + p * 16384;
        #pragma unroll
        for (int q = 0; q < 4; q++) {
            int i  = tid + q * NT1;        // 0..1023
            int r  = i >> 3;
            int ch = i & 7;
            CP_ASYNC16(sb + SWZ(r * 128 + ch * 16),
                       g_e0 + (n0 + r) * EMBED_DIM + ch * 8);
        }
    };

    load_b(0, 0);
    CP_COMMIT();

    // prologue: z tile -> fp16 A0 (swizzled)
    {
        const float* zb = z + b * (EMBED_DIM * HW) + hw0;
        #pragma unroll
        for (int q = 0; q < 8; q++) {
            int i  = tid + q * NT1;        // 0..2047
            int c  = i >> 5;
            int m4 = (i & 31) << 2;
            float4 v = *(const float4*)(zb + c * HW + m4);
            float xs[4] = {v.x, v.y, v.z, v.w};
            #pragma unroll
            for (int e = 0; e < 4; e++)
                *(__half*)(sm + SWZ((m4 + e) * 128 + c * 2)) = __float2half(xs[e]);
        }
    }
    __syncthreads();

    // per-slot: top-3 values, packed top-2 indices (lo16=i1, hi16=i2)
    float v1[4], v2[4], v3[4];
    uint32_t pk[4];
    #pragma unroll
    for (int s = 0; s < 4; s++) {
        v1[s] = v2[s] = v3[s] = -3.0e38f;
        pk[s] = 0u;
    }

    const int a_row  = wm0 + (grp & 1) * 8 + (lane & 7);
    const int b_rowL = cn0 + (grp & 1) * 8 + (lane & 7);
    const int k_off  = (grp >> 1) * 8;

    for (int t = 0; t < N_TILES; t++) {
        const int p  = t & 1;
        const int n0 = t * TN;

        if (t + 1 < N_TILES) {
            load_b(t + 1, (t + 1) & 1);
            CP_COMMIT();
            CP_WAIT1();
        } else {
            CP_WAIT0();
        }
        __syncthreads();

        float acc[2][8][4];
        #pragma unroll
        for (int i = 0; i < 2; i++)
            #pragma unroll
            for (int j = 0; j < 8; j++)
                #pragma unroll
                for (int q = 0; q < 4; q++) acc[i][j][q] = 0.0f;

        const uint32_t bbuf = abase + OFF_B + p * 16384;
        #pragma unroll
        for (int ks = 0; ks < 4; ks++) {
            const int kb = ks * 16 + k_off;
            uint32_t a0f[2][4];
            #pragma unroll
            for (int i = 0; i < 2; i++)
                LDSM_X4(a0f[i], abase + SWZ((a_row + i * 16) * 128 + kb * 2));
            #pragma unroll
            for (int j2 = 0; j2 < 4; j2++) {
                uint32_t b0r[4];
                LDSM_X4(b0r, bbuf + SWZ((b_rowL + j2 * 16) * 128 + kb * 2));
                #pragma unroll
                for (int sub = 0; sub < 2; sub++)
                    #pragma unroll
                    for (int i = 0; i < 2; i++)
                        MMA_16816(acc[i][j2 * 2 + sub], a0f[i], b0r[sub], b0r[2 + sub]);
            }
        }

        // phase 1: per-slot tile max (cheap fmax tree)
        float tm[4];
        #pragma unroll
        for (int s = 0; s < 4; s++) tm[s] = -3.0e38f;
        #pragma unroll
        for (int i = 0; i < 2; i++)
            #pragma unroll
            for (int j = 0; j < 8; j++)
                #pragma unroll
                for (int h = 0; h < 2; h++)
                    tm[i * 2 + h] = fmaxf(tm[i * 2 + h],
                                          fmaxf(acc[i][j][2 * h], acc[i][j][2 * h + 1]));

        // phase 2: insert scores only if tile can change the top-3 values.
        // Scores <= v3 cannot alter v1/v2/v3 (strict >, ascending indices).
        #pragma unroll
        for (int i = 0; i < 2; i++) {
            #pragma unroll
            for (int h = 0; h < 2; h++) {
                int s = i * 2 + h;
                if (tm[s] > v3[s]) {
                    #pragma unroll
                    for (int j = 0; j < 8; j++) {
                        int cbase = n0 + cn0 + j * 8 + (lane & 3) * 2;
                        #pragma unroll
                        for (int u = 0; u < 2; u++) {
                            float v = acc[i][j][2 * h + u];
                            if (v > v3[s]) {
                                uint32_t idx = (uint32_t)(cbase + u);
                                if (v > v1[s]) {
                                    v3[s] = v2[s]; v2[s] = v1[s]; v1[s] = v;
                                    pk[s] = ((pk[s] & 0xFFFFu) << 16) | idx;
                                } else if (v > v2[s]) {
                                    v3[s] = v2[s]; v2[s] = v;
                                    pk[s] = (pk[s] & 0xFFFFu) | (idx << 16);
                                } else {
                                    v3[s] = v;
                                }
                            }
                        }
                    }
                }
            }
        }
        __syncthreads();
    }

    // quad reduce: merge tuples across the 4 column-lanes of each token
    #pragma unroll
    for (int s = 0; s < 4; s++) {
        #pragma unroll
        for (int off = 1; off < 4; off <<= 1) {
            float    b1 = __shfl_xor_sync(0xFFFFFFFFu, v1[s], off);
            float    b2 = __shfl_xor_sync(0xFFFFFFFFu, v2[s], off);
            float    b3 = __shfl_xor_sync(0xFFFFFFFFu, v3[s], off);
            uint32_t bp = __shfl_xor_sync(0xFFFFFFFFu, pk[s], off);
            merge5(v1[s], v2[s], v3[s], pk[s], b1, b2, b3, bp);
        }
    }

    // table: [row][warp_n] = (v1, packed, v2, v3)
    float4* table = (float4*)(sm + OFF_TAB);
    if ((lane & 3) == 0) {
        #pragma unroll
        for (int s = 0; s < 4; s++) {
            int row = wm0 + (s >> 1) * 16 + (s & 1) * 8 + (lane >> 2);
            table[row * 2 + warp_n] =
                make_float4(v1[s], __uint_as_float(pk[s]), v2[s], v3[s]);
        }
    }
    __syncthreads();

    if (tid < M_CTA) {
        float4 rA = table[tid * 2 + 0];
        float4 rB = table[tid * 2 + 1];
        float    a1 = rA.x, a2 = rA.z, a3 = rA.w;
        uint32_t ap = __float_as_uint(rA.y);
        merge5(a1, a2, a3, ap, rB.x, rB.z, rB.w, __float_as_uint(rB.y));
        int i1 = (int)(ap & 0xFFFFu);
        int i2 = (int)(ap >> 16);

        // exact fp32 rescore of both candidates + ||z||^2
        const float* zb2 = z + b * (EMBED_DIM * HW) + hw0 + tid;
        const float4* e1 = (const float4*)(g_enf + i1 * EMBED_DIM);
        const float4* e2 = (const float4*)(g_enf + i2 * EMBED_DIM);
        float d1 = 0.f, d2 = 0.f, nn = 0.f;
        #pragma unroll
        for (int q = 0; q < 16; q++) {
            float z0 = zb2[(q * 4 + 0) * HW];
            float z1 = zb2[(q * 4 + 1) * HW];
            float z2 = zb2[(q * 4 + 2) * HW];
            float z3 = zb2[(q * 4 + 3) * HW];
            float4 w1 = e1[q], w2 = e2[q];
            d1 += z0 * w1.x + z1 * w1.y + z2 * w1.z + z3 * w1.w;
            d2 += z0 * w2.x + z1 * w2.y + z2 * w2.z + z3 * w2.w;
            nn += z0 * z0 + z1 * z1 + z2 * z2 + z3 * z3;
        }
        float eps = 5.2e-4f * sqrtf(nn) + 1.0e-5f;

        // exact winner among the 2 candidates (lowest index on exact tie)
        float wv = d1; int wi = i1;
        if (d2 > wv || (d2 == wv && i2 < wi)) { wv = d2; wi = i2; }

        int token = m0 + tid;
        g_idx[token] = wi;
        // all non-candidate codes: approx <= a3 -> exact <= a3 + eps
        if (wv > a3 + eps) {
            atomicAdd(&g_hist[wi], 1);
            idx_out_f[token] = (float)wi;
        } else {
            int pos = atomicAdd(&g_nflag, 1);
            g_flist[pos] = token;
        }
    }
}

// ---------------------------------------------------------------------------
// Kernel 3: exact fp32 full rescan of the (rare) uncertified tokens.
// warp per token, grid-stride. Expected count ~ tens.
// ---------------------------------------------------------------------------
__global__ __launch_bounds__(256)
void vq_fallback(const float* __restrict__ z, float* __restrict__ idx_out_f) {
    const int count = g_nflag;
    for (int i = blockIdx.x * 8 + (threadIdx.x >> 5); i < count; i += 16 * 8) {
        int lane = threadIdx.x & 31;
        int tok  = g_flist[i];
        const float* zb = z + (tok >> 12) * (EMBED_DIM * HW) + (tok & 4095);
        float zr[EMBED_DIM];
        #pragma unroll
        for (int c = 0; c < EMBED_DIM; c++) zr[c] = zb[c * HW];

        float best = -3.0e38f;
        int   bi   = 0x7FFFFFFF;
        for (int n = lane; n < NUM_EMBED; n += 32) {
            const float4* er = (const float4*)(g_enf + n * EMBED_DIM);
            float a = 0.f;
            #pragma unroll
            for (int q = 0; q < 16; q++) {
                float4 e4 = er[q];
                a += zr[q * 4 + 0] * e4.x + zr[q * 4 + 1] * e4.y
                   + zr[q * 4 + 2] * e4.z + zr[q * 4 + 3] * e4.w;
            }
            if (a > best) { best = a; bi = n; }
        }
        #pragma unroll
        for (int off = 16; off > 0; off >>= 1) {
            float ov = __shfl_xor_sync(0xFFFFFFFFu, best, off);
            int   oi = __shfl_xor_sync(0xFFFFFFFFu, bi, off);
            if (ov > best || (ov == best && oi < bi)) { best = ov; bi = oi; }
        }
        if (lane == 0) {
            g_idx[tok] = bi;
            atomicAdd(&g_hist[bi], 1);
            idx_out_f[tok] = (float)bi;
        }
    }
}

// ---------------------------------------------------------------------------
// Kernel 4: gather z_q into out, per-block loss partials
// ---------------------------------------------------------------------------
__global__ __launch_bounds__(256)
void vq_gather_loss(const float* __restrict__ z, const float* __restrict__ emb,
                    float* __restrict__ out) {
    int v = blockIdx.x * 256 + threadIdx.x;
    int e = v << 2;
    int c = (e >> 12) & 63;
    int t = ((e >> 18) << 12) | (e & 4095);

    float4 zv = *(const float4*)(z + e);
    int i0 = g_idx[t + 0];
    int i1 = g_idx[t + 1];
    int i2 = g_idx[t + 2];
    int i3 = g_idx[t + 3];
    float q0 = emb[i0 * EMBED_DIM + c];
    float q1 = emb[i1 * EMBED_DIM + c];
    float q2 = emb[i2 * EMBED_DIM + c];
    float q3 = emb[i3 * EMBED_DIM + c];
    *(float4*)(out + e) = make_float4(q0, q1, q2, q3);

    float d0 = q0 - zv.x, d1 = q1 - zv.y, d2 = q2 - zv.z, d3 = q3 - zv.w;
    float s = d0 * d0 + d1 * d1 + d2 * d2 + d3 * d3;

    #pragma unroll
    for (int o = 16; o > 0; o >>= 1) s += __shfl_xor_sync(0xFFFFFFFFu, s, o);
    __shared__ float ws[8];
    int lane = threadIdx.x & 31, wrp = threadIdx.x >> 5;
    if (lane == 0) ws[wrp] = s;
    __syncthreads();
    if (threadIdx.x == 0) {
        float acc = 0.0f;
        #pragma unroll
        for (int i = 0; i < 8; i++) acc += ws[i];
        g_partial[blockIdx.x] = acc;
    }
}

// ---------------------------------------------------------------------------
// Kernel 5: finalize loss + perplexity
// ---------------------------------------------------------------------------
__global__ __launch_bounds__(256)
void vq_finalize(float* __restrict__ out) {
    __shared__ float sh[256];
    int tid = threadIdx.x;

    float s = 0.0f;
    for (int i = tid; i < N_PART; i += 256) s += g_partial[i];
    sh[tid] = s;
    __syncthreads();
    for (int o = 128; o > 0; o >>= 1) {
        if (tid < o) sh[tid] += sh[tid + o];
        __syncthreads();
    }
    if (tid == 0) out[N_ELEM] = 1.25f * sh[0] / (float)N_ELEM;
    __syncthreads();

    float h = 0.0f;
    for (int i = tid; i < NUM_EMBED; i += 256) {
        float p = (float)g_hist[i] * (1.0f / (float)N_TOK);
        h += p * logf(p + 1e-10f);
    }
    sh[tid] = h;
    __syncthreads();
    for (int o = 128; o > 0; o >>= 1) {
        if (tid < o) sh[tid] += sh[tid + o];
        __syncthreads();
    }
    if (tid == 0) out[N_ELEM + 1] = expf(-sh[0]);
}

// ---------------------------------------------------------------------------
// Output layout (all float32): [0, N_ELEM) out | loss | perplexity | idx_map
// ---------------------------------------------------------------------------
extern "C" void kernel_launch(void* const* d_in, const int* in_sizes, int n_in,
                              void* d_out, int out_size) {
    const float* z   = (const float*)d_in[0];
    const float* emb = (const float*)d_in[1];
    float* out = (float*)d_out;

    cudaFuncSetAttribute(vq_argmax_mma, cudaFuncAttributeMaxDynamicSharedMemorySize,
                         SMEM1_BYTES);

    vq_prep_embed<<<1024, 256>>>(emb);
    vq_argmax_mma<<<N_TOK / M_CTA, NT1, SMEM1_BYTES>>>(z, out + N_ELEM + 2);
    vq_fallback<<<16, 256>>>(z, out + N_ELEM + 2);
    vq_gather_loss<<<N_PART, 256>>>(z, emb, out);
    vq_finalize<<<1, 256>>>(out);
}